// round 9
// baseline (speedup 1.0000x reference)
#include <cuda_runtime.h>
#include <cuda_fp16.h>
#include <cstdint>

// ---------------- problem constants ----------------
#define NB     65536
#define IN1    384
#define IN2    128
#define KDIM   512
#define G1U    384
#define N1     1152
#define G2U    16
#define NLEV   256

typedef unsigned long long u64;
typedef unsigned int u32;

// ---------------- device scratch ----------------
__device__ __half g_Ah[(size_t)NB * KDIM];     // 64 MB  fp16 concat(x1,x2)
__device__ __half g_Bh[(size_t)N1 * KDIM];     // reordered+transposed W1
__device__ __half g_h1h[(size_t)NB * G1U];     // 48 MB  fp16 h1
__device__ __half g_B2[(size_t)48 * G1U];      // transposed W2

// ---------------- helpers ----------------
__device__ __forceinline__ u32 smem_u32(const void* p) {
    u32 a;
    asm("{ .reg .u64 t; cvta.to.shared.u64 t, %1; cvt.u32.u64 %0, t; }" : "=r"(a) : "l"(p));
    return a;
}
__device__ __forceinline__ u32 swz(u32 x) { return x ^ ((x >> 3) & 0x70); }

#define CP_ASYNC16(dst, src) \
    asm volatile("cp.async.cg.shared.global [%0], [%1], 16;" :: "r"(dst), "l"(src) : "memory")
#define CP_COMMIT() asm volatile("cp.async.commit_group;" ::: "memory")
#define CP_WAIT0()  asm volatile("cp.async.wait_group 0;" ::: "memory")
#define CP_WAIT1()  asm volatile("cp.async.wait_group 1;" ::: "memory")

#define LDSM_X4(r0, r1, r2, r3, addr) \
    asm volatile("ldmatrix.sync.aligned.m8n8.x4.shared.b16 {%0,%1,%2,%3}, [%4];" \
        : "=r"(r0), "=r"(r1), "=r"(r2), "=r"(r3) : "r"(addr))

#define MMA16816(d, a, b) \
    asm volatile("mma.sync.aligned.m16n8k16.row.col.f32.f16.f16.f32 " \
        "{%0,%1,%2,%3},{%4,%5,%6,%7},{%8,%9},{%0,%1,%2,%3};" \
        : "+f"((d)[0]), "+f"((d)[1]), "+f"((d)[2]), "+f"((d)[3]) \
        : "r"((a)[0]), "r"((a)[1]), "r"((a)[2]), "r"((a)[3]), "r"((b)[0]), "r"((b)[1]))

// ---- fast gate math: 1 MUFU per tanh (sm_75+ tanh.approx) ----
__device__ __forceinline__ float tanh_fast(float x) {
    float y;
    asm("tanh.approx.f32 %0, %1;" : "=f"(y) : "f"(x));
    return y;
}
__device__ __forceinline__ float sigmoid_fast(float x) {
    return fmaf(0.5f, tanh_fast(0.5f * x), 0.5f);
}

// =====================================================================
// Prep 1: A = concat(x1,x2) -> fp16
// =====================================================================
__global__ __launch_bounds__(256)
void conv_a_kernel(const float* __restrict__ x1, const float* __restrict__ x2)
{
    size_t i4 = (size_t)blockIdx.x * 256 + threadIdx.x;   // 8388608 chunks of 4
    int m  = (int)(i4 >> 7);
    int c4 = ((int)i4 & 127) * 4;
    float4 v;
    if (c4 < IN1) v = *(const float4*)(x1 + (size_t)m * IN1 + c4);
    else          v = *(const float4*)(x2 + (size_t)m * IN2 + (c4 - IN1));
    size_t o = (size_t)m * KDIM + c4;
    *(__half2*)&g_Ah[o]     = __floats2half2_rn(v.x, v.y);
    *(__half2*)&g_Ah[o + 2] = __floats2half2_rn(v.z, v.w);
}

// =====================================================================
// Prep 2: W1 [512,1152] -> transposed fp16, layout n' = (j/16)*48 + g*16 + j%16
// =====================================================================
__global__ __launch_bounds__(256)
void conv_w1_kernel(const float* __restrict__ W)
{
    int idx = blockIdx.x * 256 + threadIdx.x;   // < 589824
    int k = idx / N1, c = idx % N1;
    int g = c / G1U, j = c % G1U;
    int n = (j >> 4) * 48 + g * 16 + (j & 15);
    g_Bh[(size_t)n * KDIM + k] = __float2half_rn(W[idx]);
}

// =====================================================================
// Prep 3: W2 [384,48] -> transposed fp16
// =====================================================================
__global__ __launch_bounds__(256)
void conv_w2_kernel(const float* __restrict__ W)
{
    int idx = blockIdx.x * 256 + threadIdx.x;   // < 18432
    if (idx >= G1U * 48) return;
    int k = idx / 48, c = idx % 48;
    g_B2[(size_t)c * G1U + k] = __float2half_rn(W[idx]);
}

// =====================================================================
// GEMM1: h1 = GRU1(A, h=0).  fp16 single-pass HMMA.  (R6 champion config)
// CTA tile 128 x 96; 8 warps of 32x48.  K = 512 -> 8 tiles of 64.
// 3-stage cp.async, one barrier per k-tile, 2 CTAs/SM.
// =====================================================================
#define G1_STAGE  28672            // 16KB A + 12KB B
#define G1_OFFB   16384
#define G1_NSTG   3
#define G1_BIAS   (G1_NSTG * G1_STAGE) // 86016
#define G1_SMEM   (G1_BIAS + 512)

__device__ __forceinline__ void load_stage_g1(u32 sb, int s, int kt, int m0, int nb, int tid)
{
    const int k0 = kt * 64;
    const u32 base = sb + s * G1_STAGE;
    const char* Ap = (const char*)g_Ah;
    const char* Bp = (const char*)g_Bh;
    // A tile: 128 rows x 128B
#pragma unroll
    for (int i = 0; i < 4; ++i) {
        int c = tid + i * 256;              // 0..1023
        int row = c >> 3, cb = c & 7;
        u32 dst = base + swz(row * 128 + cb * 16);
        const char* src = Ap + (size_t)(m0 + row) * (KDIM * 2) + k0 * 2 + cb * 16;
        CP_ASYNC16(dst, src);
    }
    // B tile: 96 rows x 128B
#pragma unroll
    for (int i = 0; i < 3; ++i) {
        int c = tid + i * 256;              // 0..767
        int row = c >> 3, cb = c & 7;
        u32 dst = base + G1_OFFB + swz(row * 128 + cb * 16);
        const char* src = Bp + (size_t)(nb * 96 + row) * (KDIM * 2) + k0 * 2 + cb * 16;
        CP_ASYNC16(dst, src);
    }
}

__global__ __launch_bounds__(256, 2)
void gemm1_mma_kernel(const float* __restrict__ bias)
{
    extern __shared__ char smem[];
    const u32 sb = smem_u32(smem);
    const int tid  = threadIdx.x;
    const int warp = tid >> 5, lane = tid & 31;
    const int wm = warp & 3;          // m block: 32*wm
    const int wn = warp >> 2;         // n block: 48*wn
    const int nb = blockIdx.x;        // 0..11  (32-unit block)
    const int m0 = blockIdx.y * 128;

    // stage combined biases (32 units for this CTA)
    float* czs  = (float*)(smem + G1_BIAS);
    float* crs  = czs + 32;
    float* ch0s = czs + 64;
    float* ch1s = czs + 96;
    if (tid < 32) {
        int j = nb * 32 + tid;
        czs[tid]  = bias[j]         + bias[N1 + j];
        crs[tid]  = bias[G1U + j]   + bias[N1 + G1U + j];
        ch0s[tid] = bias[2 * G1U + j];
        ch1s[tid] = bias[N1 + 2 * G1U + j];
    }

    float acc[2][6][4];
#pragma unroll
    for (int mi = 0; mi < 2; ++mi)
#pragma unroll
        for (int ni = 0; ni < 6; ++ni)
#pragma unroll
            for (int e = 0; e < 4; ++e) acc[mi][ni][e] = 0.f;

    const int a_row = 32 * wm + (lane & 15);
    const int a_kb  = (lane & 16) ? 16 : 0;
    const int b_row = 48 * wn + (lane & 7) + ((lane & 16) ? 8 : 0);
    const int b_kb  = (lane & 8) ? 16 : 0;

    // prologue: fill stages 0,1
    load_stage_g1(sb, 0, 0, m0, nb, tid); CP_COMMIT();
    load_stage_g1(sb, 1, 1, m0, nb, tid); CP_COMMIT();

    for (int kt = 0; kt < 8; ++kt) {
        const int s = kt % G1_NSTG;
        CP_WAIT1();
        __syncthreads();
        if (kt + 2 < 8) load_stage_g1(sb, (kt + 2) % G1_NSTG, kt + 2, m0, nb, tid);
        CP_COMMIT();

        const u32 abase = sb + s * G1_STAGE;
        const u32 bbase = abase + G1_OFFB;
#pragma unroll
        for (int ks = 0; ks < 4; ++ks) {
            u32 af[2][4], bf[3][4];
#pragma unroll
            for (int mi = 0; mi < 2; ++mi) {
                u32 ad = abase + swz((u32)(a_row + mi * 16) * 128 + ks * 32 + a_kb);
                LDSM_X4(af[mi][0], af[mi][1], af[mi][2], af[mi][3], ad);
            }
#pragma unroll
            for (int bi = 0; bi < 3; ++bi) {
                u32 bd = bbase + swz((u32)(b_row + bi * 16) * 128 + ks * 32 + b_kb);
                LDSM_X4(bf[bi][0], bf[bi][1], bf[bi][2], bf[bi][3], bd);
            }
#pragma unroll
            for (int mi = 0; mi < 2; ++mi)
#pragma unroll
                for (int bi = 0; bi < 3; ++bi) {
                    MMA16816(acc[mi][2 * bi],     af[mi], (&bf[bi][0]));
                    MMA16816(acc[mi][2 * bi + 1], af[mi], (&bf[bi][2]));
                }
        }
    }

    // ---- fused GRU epilogue (fast gates) ----
    const int qr = lane >> 2, qc = lane & 3;
#pragma unroll
    for (int mi = 0; mi < 2; ++mi) {
#pragma unroll
        for (int nip = 0; nip < 2; ++nip) {
            const int ul = wn * 16 + 8 * nip + 2 * qc;   // 0..31
            const int j0 = nb * 32 + ul;
            const float cz0 = czs[ul],  cz1 = czs[ul + 1];
            const float cr0 = crs[ul],  cr1 = crs[ul + 1];
            const float c00 = ch0s[ul], c01 = ch0s[ul + 1];
            const float c10 = ch1s[ul], c11 = ch1s[ul + 1];
            const float* az = acc[mi][nip];
            const float* ar = acc[mi][nip + 2];
            const float* ah = acc[mi][nip + 4];
#pragma unroll
            for (int half = 0; half < 2; ++half) {
                const int row = m0 + 32 * wm + 16 * mi + qr + half * 8;
                float z0 = sigmoid_fast(az[2 * half]     + cz0);
                float z1 = sigmoid_fast(az[2 * half + 1] + cz1);
                float r0 = sigmoid_fast(ar[2 * half]     + cr0);
                float r1 = sigmoid_fast(ar[2 * half + 1] + cr1);
                float h0 = tanh_fast(ah[2 * half]     + c00 + r0 * c10);
                float h1 = tanh_fast(ah[2 * half + 1] + c01 + r1 * c11);
                *(__half2*)&g_h1h[(size_t)row * G1U + j0] =
                    __floats2half2_rn((1.f - z0) * h0, (1.f - z1) * h1);
            }
        }
    }
}

// =====================================================================
// FUSED GEMM2 + HEAD: h2 = GRU2(h1, 0) in smem; then
// d = g1*tanh(h2@W1+b1) + g2*tanh(h2@W2+b2); softmax -> out.
// CTA = 256 thr, 128 rows. gemm2: 8 warps of 16x48, 2-stage pipeline.
// Head: warp w handles rows [16w, 16w+16), 2 at a time, from smem h2.
// =====================================================================
#define G2_STAGE  22528
#define G2_OFFB   16384
#define G2_W1     (2 * G2_STAGE)       // 45056, 16KB fp32
#define G2_W2     (G2_W1 + 16384)      // 61440
#define G2_B1     (G2_W2 + 16384)      // 77824
#define G2_B2     (G2_B1 + 1024)
#define G2_G1     (G2_B2 + 1024)
#define G2_G2     (G2_G1 + 1024)
#define G2_H2S    (G2_G2 + 1024)       // 81920, 128 x 20 floats = 10240B
#define G2_GBIAS  (G2_H2S + 10240)     // 92160, 256B
#define G2H_SMEM  (G2_GBIAS + 512)     // 92672
#define H2_STRIDE 20

__device__ __forceinline__ void load_stage_g2(u32 sb, int s, int kt, int m0, int tid)
{
    const int k0 = kt * 64;
    const u32 base = sb + s * G2_STAGE;
    const char* Ap = (const char*)g_h1h;
    const char* Bp = (const char*)g_B2;
#pragma unroll
    for (int i = 0; i < 4; ++i) {
        int c = tid + i * 256;              // 0..1023
        int row = c >> 3, cb = c & 7;
        u32 dst = base + swz(row * 128 + cb * 16);
        const char* src = Ap + (size_t)(m0 + row) * (G1U * 2) + k0 * 2 + cb * 16;
        CP_ASYNC16(dst, src);
    }
#pragma unroll
    for (int i = 0; i < 2; ++i) {
        int c = tid + i * 256;
        if (c < 384) {
            int row = c >> 3, cb = c & 7;
            u32 dst = base + G2_OFFB + swz(row * 128 + cb * 16);
            const char* src = Bp + (size_t)row * (G1U * 2) + k0 * 2 + cb * 16;
            CP_ASYNC16(dst, src);
        }
    }
}

__global__ __launch_bounds__(256, 2)
void gemm2_head_kernel(const float* __restrict__ bias,
                       const float* __restrict__ w1, const float* __restrict__ b1,
                       const float* __restrict__ w2, const float* __restrict__ b2,
                       const float* __restrict__ gv1, const float* __restrict__ gv2,
                       float* __restrict__ out)
{
    extern __shared__ char smem[];
    const u32 sb = smem_u32(smem);
    const int tid  = threadIdx.x;
    const int warp = tid >> 5, lane = tid & 31;
    const int m0 = blockIdx.x * 128;

    float* czs  = (float*)(smem + G2_GBIAS);
    float* crs  = czs + 16;
    float* ch0s = czs + 32;
    float* ch1s = czs + 48;
    if (tid < 16) {
        czs[tid]  = bias[tid]      + bias[48 + tid];
        crs[tid]  = bias[16 + tid] + bias[64 + tid];
        ch0s[tid] = bias[32 + tid];
        ch1s[tid] = bias[80 + tid];
    }

    // pipeline prologue
    load_stage_g2(sb, 0, 0, m0, tid);
    CP_COMMIT();

    // stage head weights (overlaps with cp.async fills)
    {
        float* W1s = (float*)(smem + G2_W1);
        float* W2s = (float*)(smem + G2_W2);
        const float4* w1v = (const float4*)w1;
        const float4* w2v = (const float4*)w2;
#pragma unroll
        for (int i = tid; i < 1024; i += 256) {
            ((float4*)W1s)[i] = w1v[i];
            ((float4*)W2s)[i] = w2v[i];
        }
        ((float*)(smem + G2_B1))[tid] = b1[tid];
        ((float*)(smem + G2_B2))[tid] = b2[tid];
        ((float*)(smem + G2_G1))[tid] = gv1[tid];
        ((float*)(smem + G2_G2))[tid] = gv2[tid];
    }

    CP_WAIT0();
    __syncthreads();

    float acc[6][4];
#pragma unroll
    for (int ni = 0; ni < 6; ++ni)
#pragma unroll
        for (int e = 0; e < 4; ++e) acc[ni][e] = 0.f;

    const int a_row = 16 * warp + (lane & 15);
    const int a_kb  = (lane & 16) ? 16 : 0;
    const int b_row = (lane & 7) + ((lane & 16) ? 8 : 0);
    const int b_kb  = (lane & 8) ? 16 : 0;

    for (int kt = 0; kt < 6; ++kt) {
        const int s = kt & 1;
        if (kt + 1 < 6) load_stage_g2(sb, (kt + 1) & 1, kt + 1, m0, tid);
        CP_COMMIT();

        const u32 abase = sb + s * G2_STAGE;
        const u32 bbase = abase + G2_OFFB;
#pragma unroll
        for (int ks = 0; ks < 4; ++ks) {
            u32 af[4], bf[3][4];
            u32 ad = abase + swz((u32)a_row * 128 + ks * 32 + a_kb);
            LDSM_X4(af[0], af[1], af[2], af[3], ad);
#pragma unroll
            for (int bi = 0; bi < 3; ++bi) {
                u32 bd = bbase + swz((u32)(b_row + bi * 16) * 128 + ks * 32 + b_kb);
                LDSM_X4(bf[bi][0], bf[bi][1], bf[bi][2], bf[bi][3], bd);
            }
#pragma unroll
            for (int bi = 0; bi < 3; ++bi) {
                MMA16816(acc[2 * bi],     af, (&bf[bi][0]));
                MMA16816(acc[2 * bi + 1], af, (&bf[bi][2]));
            }
        }
        CP_WAIT0();
        __syncthreads();
    }

    // ---- GRU epilogue -> h2 in smem ----
    float* h2s = (float*)(smem + G2_H2S);
    const int qr = lane >> 2, qc = lane & 3;
#pragma unroll
    for (int nip = 0; nip < 2; ++nip) {
        const int u0 = 8 * nip + 2 * qc;
        const float cz0 = czs[u0],  cz1 = czs[u0 + 1];
        const float cr0 = crs[u0],  cr1 = crs[u0 + 1];
        const float c00 = ch0s[u0], c01 = ch0s[u0 + 1];
        const float c10 = ch1s[u0], c11 = ch1s[u0 + 1];
        const float* az = acc[nip];
        const float* ar = acc[nip + 2];
        const float* ah = acc[nip + 4];
#pragma unroll
        for (int half = 0; half < 2; ++half) {
            const int lrow = 16 * warp + qr + half * 8;   // local row 0..127
            float z0 = sigmoid_fast(az[2 * half]     + cz0);
            float z1 = sigmoid_fast(az[2 * half + 1] + cz1);
            float r0 = sigmoid_fast(ar[2 * half]     + cr0);
            float r1 = sigmoid_fast(ar[2 * half + 1] + cr1);
            float h0 = tanh_fast(ah[2 * half]     + c00 + r0 * c10);
            float h1 = tanh_fast(ah[2 * half + 1] + c01 + r1 * c11);
            *(float2*)&h2s[lrow * H2_STRIDE + u0] =
                make_float2((1.f - z0) * h0, (1.f - z1) * h1);
        }
    }
    __syncthreads();

    // ---- head phase: warp w -> rows [16w, 16w+16), 2 at a time ----
    const float* W1s = (const float*)(smem + G2_W1);
    const float* W2s = (const float*)(smem + G2_W2);
    const float* b1s = (const float*)(smem + G2_B1);
    const float* b2s = (const float*)(smem + G2_B2);
    const float* g1s = (const float*)(smem + G2_G1);
    const float* g2s = (const float*)(smem + G2_G2);

    for (int p = 0; p < 8; ++p) {
        const int lr0 = 16 * warp + 2 * p;
        float ha[16], hb[16];
#pragma unroll
        for (int i = 0; i < 4; ++i) {
            float4 va = *(const float4*)&h2s[lr0 * H2_STRIDE + 4 * i];
            float4 vb = *(const float4*)&h2s[(lr0 + 1) * H2_STRIDE + 4 * i];
            ha[4*i] = va.x; ha[4*i+1] = va.y; ha[4*i+2] = va.z; ha[4*i+3] = va.w;
            hb[4*i] = vb.x; hb[4*i+1] = vb.y; hb[4*i+2] = vb.z; hb[4*i+3] = vb.w;
        }
        float a1a[8], a2a[8], a1b[8], a2b[8];
#pragma unroll
        for (int q = 0; q < 8; ++q) { a1a[q]=0.f; a2a[q]=0.f; a1b[q]=0.f; a2b[q]=0.f; }
#pragma unroll
        for (int k = 0; k < 16; ++k) {
            const float hka = ha[k], hkb = hb[k];
#pragma unroll
            for (int q = 0; q < 8; ++q) {
                const int l = lane + 32 * q;
                const float wv1 = W1s[k * NLEV + l];
                const float wv2 = W2s[k * NLEV + l];
                a1a[q] = fmaf(hka, wv1, a1a[q]);
                a2a[q] = fmaf(hka, wv2, a2a[q]);
                a1b[q] = fmaf(hkb, wv1, a1b[q]);
                a2b[q] = fmaf(hkb, wv2, a2b[q]);
            }
        }
#pragma unroll
        for (int ri = 0; ri < 2; ++ri) {
            float v[8];
#pragma unroll
            for (int q = 0; q < 8; ++q) {
                const int l = lane + 32 * q;
                const float t1 = tanh_fast((ri ? a1b[q] : a1a[q]) + b1s[l]);
                const float t2 = tanh_fast((ri ? a2b[q] : a2a[q]) + b2s[l]);
                v[q] = g1s[l] * t1 + g2s[l] * t2;
            }
            float mx = v[0];
#pragma unroll
            for (int q = 1; q < 8; ++q) mx = fmaxf(mx, v[q]);
#pragma unroll
            for (int off = 16; off >= 1; off >>= 1)
                mx = fmaxf(mx, __shfl_xor_sync(0xffffffffu, mx, off));
            float e[8], s = 0.f;
#pragma unroll
            for (int q = 0; q < 8; ++q) { e[q] = __expf(v[q] - mx); s += e[q]; }
#pragma unroll
            for (int off = 16; off >= 1; off >>= 1)
                s += __shfl_xor_sync(0xffffffffu, s, off);
            const float inv = 1.0f / s;
            float* orow = out + (size_t)(m0 + lr0 + ri) * NLEV;
#pragma unroll
            for (int q = 0; q < 8; ++q)
                orow[lane + 32 * q] = e[q] * inv;
        }
    }
}

// =====================================================================
extern "C" void kernel_launch(void* const* d_in, const int* in_sizes, int n_in,
                              void* d_out, int out_size)
{
    const float* x1   = (const float*)d_in[0];
    const float* x2   = (const float*)d_in[1];
    const float* g1k  = (const float*)d_in[2];
    const float* g1b  = (const float*)d_in[4];
    const float* g2k  = (const float*)d_in[5];
    const float* g2b  = (const float*)d_in[7];
    const float* fw1  = (const float*)d_in[8];
    const float* fb1  = (const float*)d_in[9];
    const float* fw2  = (const float*)d_in[10];
    const float* fb2  = (const float*)d_in[11];
    const float* fg1  = (const float*)d_in[12];
    const float* fg2  = (const float*)d_in[13];
    float* out = (float*)d_out;

    cudaFuncSetAttribute(gemm1_mma_kernel,
                         cudaFuncAttributeMaxDynamicSharedMemorySize, G1_SMEM);
    cudaFuncSetAttribute(gemm2_head_kernel,
                         cudaFuncAttributeMaxDynamicSharedMemorySize, G2H_SMEM);

    conv_a_kernel<<<(NB * (KDIM / 4)) / 256, 256>>>(x1, x2);
    conv_w1_kernel<<<(KDIM * N1) / 256, 256>>>(g1k);
    conv_w2_kernel<<<(G1U * 48 + 255) / 256, 256>>>(g2k);
    gemm1_mma_kernel<<<dim3(12, NB / 128), 256, G1_SMEM>>>(g1b);
    gemm2_head_kernel<<<NB / 128, 256, G2H_SMEM>>>(g2b, fw1, fb1, fw2, fb2, fg1, fg2, out);
}

// round 10
// speedup vs baseline: 1.3256x; 1.3256x over previous
#include <cuda_runtime.h>
#include <cuda_fp16.h>
#include <cstdint>

// ---------------- problem constants ----------------
#define NB     65536
#define IN1    384
#define IN2    128
#define KDIM   512
#define G1U    384
#define N1     1152
#define G2U    16
#define NLEV   256

typedef unsigned long long u64;
typedef unsigned int u32;

// ---------------- device scratch ----------------
__device__ __half g_Ah[(size_t)NB * KDIM];     // 64 MB  fp16 concat(x1,x2)
__device__ __half g_Bh[(size_t)N1 * KDIM];     // reordered+transposed W1
__device__ __half g_h1h[(size_t)NB * G1U];     // 48 MB  fp16 h1
__device__ __half g_B2[(size_t)48 * G1U];      // transposed W2
__device__ float  g_h2[(size_t)NB * G2U];      // 4 MB   fp32 h2

// ---------------- helpers ----------------
__device__ __forceinline__ u32 smem_u32(const void* p) {
    u32 a;
    asm("{ .reg .u64 t; cvta.to.shared.u64 t, %1; cvt.u32.u64 %0, t; }" : "=r"(a) : "l"(p));
    return a;
}
__device__ __forceinline__ u32 swz(u32 x) { return x ^ ((x >> 3) & 0x70); }

#define CP_ASYNC16(dst, src) \
    asm volatile("cp.async.cg.shared.global [%0], [%1], 16;" :: "r"(dst), "l"(src) : "memory")
#define CP_COMMIT() asm volatile("cp.async.commit_group;" ::: "memory")
#define CP_WAIT1()  asm volatile("cp.async.wait_group 1;" ::: "memory")

#define LDSM_X4(r0, r1, r2, r3, addr) \
    asm volatile("ldmatrix.sync.aligned.m8n8.x4.shared.b16 {%0,%1,%2,%3}, [%4];" \
        : "=r"(r0), "=r"(r1), "=r"(r2), "=r"(r3) : "r"(addr))

#define MMA16816(d, a, b) \
    asm volatile("mma.sync.aligned.m16n8k16.row.col.f32.f16.f16.f32 " \
        "{%0,%1,%2,%3},{%4,%5,%6,%7},{%8,%9},{%0,%1,%2,%3};" \
        : "+f"((d)[0]), "+f"((d)[1]), "+f"((d)[2]), "+f"((d)[3]) \
        : "r"((a)[0]), "r"((a)[1]), "r"((a)[2]), "r"((a)[3]), "r"((b)[0]), "r"((b)[1]))

// ---- fast gate math: 1 MUFU per tanh (sm_75+ tanh.approx) ----
__device__ __forceinline__ float tanh_fast(float x) {
    float y;
    asm("tanh.approx.f32 %0, %1;" : "=f"(y) : "f"(x));
    return y;
}
__device__ __forceinline__ float sigmoid_fast(float x) {
    return fmaf(0.5f, tanh_fast(0.5f * x), 0.5f);
}

// =====================================================================
// Prep 1: A = concat(x1,x2) -> fp16
// =====================================================================
__global__ __launch_bounds__(256)
void conv_a_kernel(const float* __restrict__ x1, const float* __restrict__ x2)
{
    size_t i4 = (size_t)blockIdx.x * 256 + threadIdx.x;   // 8388608 chunks of 4
    int m  = (int)(i4 >> 7);
    int c4 = ((int)i4 & 127) * 4;
    float4 v;
    if (c4 < IN1) v = *(const float4*)(x1 + (size_t)m * IN1 + c4);
    else          v = *(const float4*)(x2 + (size_t)m * IN2 + (c4 - IN1));
    size_t o = (size_t)m * KDIM + c4;
    *(__half2*)&g_Ah[o]     = __floats2half2_rn(v.x, v.y);
    *(__half2*)&g_Ah[o + 2] = __floats2half2_rn(v.z, v.w);
}

// =====================================================================
// Prep 2: W1 [512,1152] -> transposed fp16, layout n' = (j/16)*48 + g*16 + j%16
// =====================================================================
__global__ __launch_bounds__(256)
void conv_w1_kernel(const float* __restrict__ W)
{
    int idx = blockIdx.x * 256 + threadIdx.x;   // < 589824
    int k = idx / N1, c = idx % N1;
    int g = c / G1U, j = c % G1U;
    int n = (j >> 4) * 48 + g * 16 + (j & 15);
    g_Bh[(size_t)n * KDIM + k] = __float2half_rn(W[idx]);
}

// =====================================================================
// Prep 3: W2 [384,48] -> transposed fp16
// =====================================================================
__global__ __launch_bounds__(256)
void conv_w2_kernel(const float* __restrict__ W)
{
    int idx = blockIdx.x * 256 + threadIdx.x;   // < 18432
    if (idx >= G1U * 48) return;
    int k = idx / 48, c = idx % 48;
    g_B2[(size_t)c * G1U + k] = __float2half_rn(W[idx]);
}

// =====================================================================
// GEMM1: h1 = GRU1(A, h=0).  fp16 single-pass HMMA.  (champion config)
// CTA tile 128 x 96; 8 warps of 32x48.  K = 512 -> 8 tiles of 64.
// 3-stage cp.async, one barrier per k-tile, 2 CTAs/SM, fast gates.
// =====================================================================
#define G1_STAGE  28672            // 16KB A + 12KB B
#define G1_OFFB   16384
#define G1_NSTG   3
#define G1_BIAS   (G1_NSTG * G1_STAGE) // 86016
#define G1_SMEM   (G1_BIAS + 512)

__device__ __forceinline__ void load_stage_g1(u32 sb, int s, int kt, int m0, int nb, int tid)
{
    const int k0 = kt * 64;
    const u32 base = sb + s * G1_STAGE;
    const char* Ap = (const char*)g_Ah;
    const char* Bp = (const char*)g_Bh;
    // A tile: 128 rows x 128B
#pragma unroll
    for (int i = 0; i < 4; ++i) {
        int c = tid + i * 256;              // 0..1023
        int row = c >> 3, cb = c & 7;
        u32 dst = base + swz(row * 128 + cb * 16);
        const char* src = Ap + (size_t)(m0 + row) * (KDIM * 2) + k0 * 2 + cb * 16;
        CP_ASYNC16(dst, src);
    }
    // B tile: 96 rows x 128B
#pragma unroll
    for (int i = 0; i < 3; ++i) {
        int c = tid + i * 256;              // 0..767
        int row = c >> 3, cb = c & 7;
        u32 dst = base + G1_OFFB + swz(row * 128 + cb * 16);
        const char* src = Bp + (size_t)(nb * 96 + row) * (KDIM * 2) + k0 * 2 + cb * 16;
        CP_ASYNC16(dst, src);
    }
}

__global__ __launch_bounds__(256, 2)
void gemm1_mma_kernel(const float* __restrict__ bias)
{
    extern __shared__ char smem[];
    const u32 sb = smem_u32(smem);
    const int tid  = threadIdx.x;
    const int warp = tid >> 5, lane = tid & 31;
    const int wm = warp & 3;          // m block: 32*wm
    const int wn = warp >> 2;         // n block: 48*wn
    const int nb = blockIdx.x;        // 0..11  (32-unit block)
    const int m0 = blockIdx.y * 128;

    // stage combined biases (32 units for this CTA)
    float* czs  = (float*)(smem + G1_BIAS);
    float* crs  = czs + 32;
    float* ch0s = czs + 64;
    float* ch1s = czs + 96;
    if (tid < 32) {
        int j = nb * 32 + tid;
        czs[tid]  = bias[j]         + bias[N1 + j];
        crs[tid]  = bias[G1U + j]   + bias[N1 + G1U + j];
        ch0s[tid] = bias[2 * G1U + j];
        ch1s[tid] = bias[N1 + 2 * G1U + j];
    }

    float acc[2][6][4];
#pragma unroll
    for (int mi = 0; mi < 2; ++mi)
#pragma unroll
        for (int ni = 0; ni < 6; ++ni)
#pragma unroll
            for (int e = 0; e < 4; ++e) acc[mi][ni][e] = 0.f;

    const int a_row = 32 * wm + (lane & 15);
    const int a_kb  = (lane & 16) ? 16 : 0;
    const int b_row = 48 * wn + (lane & 7) + ((lane & 16) ? 8 : 0);
    const int b_kb  = (lane & 8) ? 16 : 0;

    // prologue: fill stages 0,1
    load_stage_g1(sb, 0, 0, m0, nb, tid); CP_COMMIT();
    load_stage_g1(sb, 1, 1, m0, nb, tid); CP_COMMIT();

    for (int kt = 0; kt < 8; ++kt) {
        const int s = kt % G1_NSTG;
        CP_WAIT1();
        __syncthreads();
        if (kt + 2 < 8) load_stage_g1(sb, (kt + 2) % G1_NSTG, kt + 2, m0, nb, tid);
        CP_COMMIT();

        const u32 abase = sb + s * G1_STAGE;
        const u32 bbase = abase + G1_OFFB;
#pragma unroll
        for (int ks = 0; ks < 4; ++ks) {
            u32 af[2][4], bf[3][4];
#pragma unroll
            for (int mi = 0; mi < 2; ++mi) {
                u32 ad = abase + swz((u32)(a_row + mi * 16) * 128 + ks * 32 + a_kb);
                LDSM_X4(af[mi][0], af[mi][1], af[mi][2], af[mi][3], ad);
            }
#pragma unroll
            for (int bi = 0; bi < 3; ++bi) {
                u32 bd = bbase + swz((u32)(b_row + bi * 16) * 128 + ks * 32 + b_kb);
                LDSM_X4(bf[bi][0], bf[bi][1], bf[bi][2], bf[bi][3], bd);
            }
#pragma unroll
            for (int mi = 0; mi < 2; ++mi)
#pragma unroll
                for (int bi = 0; bi < 3; ++bi) {
                    MMA16816(acc[mi][2 * bi],     af[mi], (&bf[bi][0]));
                    MMA16816(acc[mi][2 * bi + 1], af[mi], (&bf[bi][2]));
                }
        }
    }

    // ---- fused GRU epilogue (fast gates) ----
    const int qr = lane >> 2, qc = lane & 3;
#pragma unroll
    for (int mi = 0; mi < 2; ++mi) {
#pragma unroll
        for (int nip = 0; nip < 2; ++nip) {
            const int ul = wn * 16 + 8 * nip + 2 * qc;   // 0..31
            const int j0 = nb * 32 + ul;
            const float cz0 = czs[ul],  cz1 = czs[ul + 1];
            const float cr0 = crs[ul],  cr1 = crs[ul + 1];
            const float c00 = ch0s[ul], c01 = ch0s[ul + 1];
            const float c10 = ch1s[ul], c11 = ch1s[ul + 1];
            const float* az = acc[mi][nip];
            const float* ar = acc[mi][nip + 2];
            const float* ah = acc[mi][nip + 4];
#pragma unroll
            for (int half = 0; half < 2; ++half) {
                const int row = m0 + 32 * wm + 16 * mi + qr + half * 8;
                float z0 = sigmoid_fast(az[2 * half]     + cz0);
                float z1 = sigmoid_fast(az[2 * half + 1] + cz1);
                float r0 = sigmoid_fast(ar[2 * half]     + cr0);
                float r1 = sigmoid_fast(ar[2 * half + 1] + cr1);
                float h0 = tanh_fast(ah[2 * half]     + c00 + r0 * c10);
                float h1 = tanh_fast(ah[2 * half + 1] + c01 + r1 * c11);
                *(__half2*)&g_h1h[(size_t)row * G1U + j0] =
                    __floats2half2_rn((1.f - z0) * h0, (1.f - z1) * h1);
            }
        }
    }
}

// =====================================================================
// GEMM2: h2 = GRU2(h1, h=0).  fp16 single-pass HMMA.  (R6 config + fast gates)
// CTA tile 128 x 48; 8 warps of 16x48. K = 384 -> 6 tiles; 3-stage.
// =====================================================================
#define G2_STAGE  22528          // 16KB A + 6KB B (padded)
#define G2_OFFB   16384
#define G2_BIAS   (3 * G2_STAGE) // 67584
#define G2_SMEM   (G2_BIAS + 512)

__device__ __forceinline__ void load_stage_g2(u32 sb, int s, int kt, int m0, int tid)
{
    const int k0 = kt * 64;
    const u32 base = sb + s * G2_STAGE;
    const char* Ap = (const char*)g_h1h;
    const char* Bp = (const char*)g_B2;
#pragma unroll
    for (int i = 0; i < 4; ++i) {
        int c = tid + i * 256;              // 0..1023
        int row = c >> 3, cb = c & 7;
        u32 dst = base + swz(row * 128 + cb * 16);
        const char* src = Ap + (size_t)(m0 + row) * (G1U * 2) + k0 * 2 + cb * 16;
        CP_ASYNC16(dst, src);
    }
#pragma unroll
    for (int i = 0; i < 2; ++i) {
        int c = tid + i * 256;
        if (c < 384) {
            int row = c >> 3, cb = c & 7;
            u32 dst = base + G2_OFFB + swz(row * 128 + cb * 16);
            const char* src = Bp + (size_t)row * (G1U * 2) + k0 * 2 + cb * 16;
            CP_ASYNC16(dst, src);
        }
    }
}

__global__ __launch_bounds__(256, 2)
void gemm2_mma_kernel(const float* __restrict__ bias)
{
    extern __shared__ char smem[];
    const u32 sb = smem_u32(smem);
    const int tid  = threadIdx.x;
    const int warp = tid >> 5, lane = tid & 31;
    const int m0 = blockIdx.x * 128;

    float* czs  = (float*)(smem + G2_BIAS);
    float* crs  = czs + 16;
    float* ch0s = czs + 32;
    float* ch1s = czs + 48;
    if (tid < 16) {
        czs[tid]  = bias[tid]      + bias[48 + tid];
        crs[tid]  = bias[16 + tid] + bias[64 + tid];
        ch0s[tid] = bias[32 + tid];
        ch1s[tid] = bias[80 + tid];
    }

    float acc[6][4];
#pragma unroll
    for (int ni = 0; ni < 6; ++ni)
#pragma unroll
        for (int e = 0; e < 4; ++e) acc[ni][e] = 0.f;

    const int a_row = 16 * warp + (lane & 15);
    const int a_kb  = (lane & 16) ? 16 : 0;
    const int b_row = (lane & 7) + ((lane & 16) ? 8 : 0);
    const int b_kb  = (lane & 8) ? 16 : 0;

    load_stage_g2(sb, 0, 0, m0, tid); CP_COMMIT();
    load_stage_g2(sb, 1, 1, m0, tid); CP_COMMIT();

    for (int kt = 0; kt < 6; ++kt) {
        const int s = kt % 3;
        CP_WAIT1();
        __syncthreads();
        if (kt + 2 < 6) load_stage_g2(sb, (kt + 2) % 3, kt + 2, m0, tid);
        CP_COMMIT();

        const u32 abase = sb + s * G2_STAGE;
        const u32 bbase = abase + G2_OFFB;
#pragma unroll
        for (int ks = 0; ks < 4; ++ks) {
            u32 af[4], bf[3][4];
            u32 ad = abase + swz((u32)a_row * 128 + ks * 32 + a_kb);
            LDSM_X4(af[0], af[1], af[2], af[3], ad);
#pragma unroll
            for (int bi = 0; bi < 3; ++bi) {
                u32 bd = bbase + swz((u32)(b_row + bi * 16) * 128 + ks * 32 + b_kb);
                LDSM_X4(bf[bi][0], bf[bi][1], bf[bi][2], bf[bi][3], bd);
            }
#pragma unroll
            for (int bi = 0; bi < 3; ++bi) {
                MMA16816(acc[2 * bi],     af, (&bf[bi][0]));
                MMA16816(acc[2 * bi + 1], af, (&bf[bi][2]));
            }
        }
    }

    const int qr = lane >> 2, qc = lane & 3;
#pragma unroll
    for (int nip = 0; nip < 2; ++nip) {
        const int u0 = 8 * nip + 2 * qc;
        const float cz0 = czs[u0],  cz1 = czs[u0 + 1];
        const float cr0 = crs[u0],  cr1 = crs[u0 + 1];
        const float c00 = ch0s[u0], c01 = ch0s[u0 + 1];
        const float c10 = ch1s[u0], c11 = ch1s[u0 + 1];
        const float* az = acc[nip];
        const float* ar = acc[nip + 2];
        const float* ah = acc[nip + 4];
#pragma unroll
        for (int half = 0; half < 2; ++half) {
            const int row = m0 + 16 * warp + qr + half * 8;
            float z0 = sigmoid_fast(az[2 * half]     + cz0);
            float z1 = sigmoid_fast(az[2 * half + 1] + cz1);
            float r0 = sigmoid_fast(ar[2 * half]     + cr0);
            float r1 = sigmoid_fast(ar[2 * half + 1] + cr1);
            float h0 = tanh_fast(ah[2 * half]     + c00 + r0 * c10);
            float h1 = tanh_fast(ah[2 * half + 1] + c01 + r1 * c11);
            *(float2*)&g_h2[(size_t)row * G2U + u0] =
                make_float2((1.f - z0) * h0, (1.f - z1) * h1);
        }
    }
}

// =====================================================================
// Kernel 3: head + softmax. One warp per 8 rows (2 at a time), fast tanh.
// =====================================================================
__global__ __launch_bounds__(256)
void head_kernel(const float* __restrict__ w1, const float* __restrict__ b1,
                 const float* __restrict__ w2, const float* __restrict__ b2,
                 const float* __restrict__ gv1, const float* __restrict__ gv2,
                 float* __restrict__ out)
{
    __shared__ float W1s[16 * NLEV];
    __shared__ float W2s[16 * NLEV];
    __shared__ float b1s[NLEV], b2s[NLEV], g1s[NLEV], g2s[NLEV];

    const int t = threadIdx.x;
    for (int i = t; i < 16 * NLEV; i += 256) { W1s[i] = w1[i]; W2s[i] = w2[i]; }
    b1s[t] = b1[t]; b2s[t] = b2[t]; g1s[t] = gv1[t]; g2s[t] = gv2[t];
    __syncthreads();

    const int warp = t >> 5, lane = t & 31;
    const int gwarp = blockIdx.x * 8 + warp;

    for (int p = 0; p < 4; ++p) {
        const int r0 = gwarp * 8 + p * 2;
        float ha[16], hb[16];
        {
            const float4* pa = (const float4*)&g_h2[(size_t)r0 * G2U];
            const float4* pb = (const float4*)&g_h2[(size_t)(r0 + 1) * G2U];
#pragma unroll
            for (int i = 0; i < 4; ++i) {
                float4 va = __ldg(pa + i);
                float4 vb = __ldg(pb + i);
                ha[4*i] = va.x; ha[4*i+1] = va.y; ha[4*i+2] = va.z; ha[4*i+3] = va.w;
                hb[4*i] = vb.x; hb[4*i+1] = vb.y; hb[4*i+2] = vb.z; hb[4*i+3] = vb.w;
            }
        }
        float a1a[8], a2a[8], a1b[8], a2b[8];
#pragma unroll
        for (int q = 0; q < 8; ++q) { a1a[q]=0.f; a2a[q]=0.f; a1b[q]=0.f; a2b[q]=0.f; }
#pragma unroll
        for (int k = 0; k < 16; ++k) {
            const float hka = ha[k], hkb = hb[k];
#pragma unroll
            for (int q = 0; q < 8; ++q) {
                const int l = lane + 32 * q;
                const float wv1 = W1s[k * NLEV + l];
                const float wv2 = W2s[k * NLEV + l];
                a1a[q] = fmaf(hka, wv1, a1a[q]);
                a2a[q] = fmaf(hka, wv2, a2a[q]);
                a1b[q] = fmaf(hkb, wv1, a1b[q]);
                a2b[q] = fmaf(hkb, wv2, a2b[q]);
            }
        }
#pragma unroll
        for (int ri = 0; ri < 2; ++ri) {
            float v[8];
#pragma unroll
            for (int q = 0; q < 8; ++q) {
                const int l = lane + 32 * q;
                const float t1 = tanh_fast((ri ? a1b[q] : a1a[q]) + b1s[l]);
                const float t2 = tanh_fast((ri ? a2b[q] : a2a[q]) + b2s[l]);
                v[q] = g1s[l] * t1 + g2s[l] * t2;
            }
            float mx = v[0];
#pragma unroll
            for (int q = 1; q < 8; ++q) mx = fmaxf(mx, v[q]);
#pragma unroll
            for (int off = 16; off >= 1; off >>= 1)
                mx = fmaxf(mx, __shfl_xor_sync(0xffffffffu, mx, off));
            float e[8], s = 0.f;
#pragma unroll
            for (int q = 0; q < 8; ++q) { e[q] = __expf(v[q] - mx); s += e[q]; }
#pragma unroll
            for (int off = 16; off >= 1; off >>= 1)
                s += __shfl_xor_sync(0xffffffffu, s, off);
            const float inv = 1.0f / s;
            float* orow = out + (size_t)(r0 + ri) * NLEV;
#pragma unroll
            for (int q = 0; q < 8; ++q)
                orow[lane + 32 * q] = e[q] * inv;
        }
    }
}

// =====================================================================
extern "C" void kernel_launch(void* const* d_in, const int* in_sizes, int n_in,
                              void* d_out, int out_size)
{
    const float* x1   = (const float*)d_in[0];
    const float* x2   = (const float*)d_in[1];
    const float* g1k  = (const float*)d_in[2];
    const float* g1b  = (const float*)d_in[4];
    const float* g2k  = (const float*)d_in[5];
    const float* g2b  = (const float*)d_in[7];
    const float* fw1  = (const float*)d_in[8];
    const float* fb1  = (const float*)d_in[9];
    const float* fw2  = (const float*)d_in[10];
    const float* fb2  = (const float*)d_in[11];
    const float* fg1  = (const float*)d_in[12];
    const float* fg2  = (const float*)d_in[13];
    float* out = (float*)d_out;

    cudaFuncSetAttribute(gemm1_mma_kernel,
                         cudaFuncAttributeMaxDynamicSharedMemorySize, G1_SMEM);
    cudaFuncSetAttribute(gemm2_mma_kernel,
                         cudaFuncAttributeMaxDynamicSharedMemorySize, G2_SMEM);

    conv_a_kernel<<<(NB * (KDIM / 4)) / 256, 256>>>(x1, x2);
    conv_w1_kernel<<<(KDIM * N1) / 256, 256>>>(g1k);
    conv_w2_kernel<<<(G1U * 48 + 255) / 256, 256>>>(g2k);
    gemm1_mma_kernel<<<dim3(12, NB / 128), 256, G1_SMEM>>>(g1b);
    gemm2_mma_kernel<<<NB / 128, 256, G2_SMEM>>>(g2b);
    head_kernel<<<NB / 64, 256>>>(fw1, fb1, fw2, fb2, fg1, fg2, out);
}

// round 11
// speedup vs baseline: 1.3720x; 1.0350x over previous
#include <cuda_runtime.h>
#include <cuda_fp16.h>
#include <cstdint>

// ---------------- problem constants ----------------
#define NB     65536
#define IN1    384
#define IN2    128
#define KDIM   512
#define G1U    384
#define N1     1152
#define G2U    16
#define NLEV   256

typedef unsigned long long u64;
typedef unsigned int u32;

// ---------------- device scratch ----------------
__device__ __half g_Ah[(size_t)NB * KDIM];     // 64 MB  fp16 concat(x1,x2)
__device__ __half g_Bh[(size_t)N1 * KDIM];     // reordered+transposed W1
__device__ __half g_h1h[(size_t)NB * G1U];     // 48 MB  fp16 h1
__device__ __half g_B2[(size_t)48 * G1U];      // transposed W2
__device__ float  g_h2[(size_t)NB * G2U];      // 4 MB   fp32 h2
__device__ __half2 g_Wh[16 * NLEV];            // packed (w1,w2) head weights

// ---------------- helpers ----------------
__device__ __forceinline__ u32 smem_u32(const void* p) {
    u32 a;
    asm("{ .reg .u64 t; cvta.to.shared.u64 t, %1; cvt.u32.u64 %0, t; }" : "=r"(a) : "l"(p));
    return a;
}
__device__ __forceinline__ u32 swz(u32 x) { return x ^ ((x >> 3) & 0x70); }

#define CP_ASYNC16(dst, src) \
    asm volatile("cp.async.cg.shared.global [%0], [%1], 16;" :: "r"(dst), "l"(src) : "memory")
#define CP_COMMIT() asm volatile("cp.async.commit_group;" ::: "memory")
#define CP_WAIT1()  asm volatile("cp.async.wait_group 1;" ::: "memory")

#define LDSM_X4(r0, r1, r2, r3, addr) \
    asm volatile("ldmatrix.sync.aligned.m8n8.x4.shared.b16 {%0,%1,%2,%3}, [%4];" \
        : "=r"(r0), "=r"(r1), "=r"(r2), "=r"(r3) : "r"(addr))

#define MMA16816(d, a, b) \
    asm volatile("mma.sync.aligned.m16n8k16.row.col.f32.f16.f16.f32 " \
        "{%0,%1,%2,%3},{%4,%5,%6,%7},{%8,%9},{%0,%1,%2,%3};" \
        : "+f"((d)[0]), "+f"((d)[1]), "+f"((d)[2]), "+f"((d)[3]) \
        : "r"((a)[0]), "r"((a)[1]), "r"((a)[2]), "r"((a)[3]), "r"((b)[0]), "r"((b)[1]))

// ---- fast gate math: 1 MUFU per tanh ----
__device__ __forceinline__ float tanh_fast(float x) {
    float y;
    asm("tanh.approx.f32 %0, %1;" : "=f"(y) : "f"(x));
    return y;
}
__device__ __forceinline__ float sigmoid_fast(float x) {
    return fmaf(0.5f, tanh_fast(0.5f * x), 0.5f);
}

// =====================================================================
// Combined prep kernel (single launch):
//  blocks [0, NBA)            : A = concat(x1,x2) -> fp16
//  blocks [NBA, NBA+NBW1)     : W1 transpose+reorder -> fp16
//  blocks [.., +NBW2)         : W2 transpose -> fp16
//  last block                 : pack head weights (w1,w2) -> half2
// =====================================================================
#define NBA   (NB * (KDIM / 4) / 256)     // 16384
#define NBW1  ((KDIM * N1) / 256)         // 2304
#define NBW2  ((G1U * 48 + 255) / 256)    // 72
#define NPREP (NBA + NBW1 + NBW2 + 1)

__global__ __launch_bounds__(256)
void prep_kernel(const float* __restrict__ x1, const float* __restrict__ x2,
                 const float* __restrict__ W1, const float* __restrict__ W2,
                 const float* __restrict__ hw1, const float* __restrict__ hw2)
{
    const int b = blockIdx.x;
    const int t = threadIdx.x;
    if (b < NBA) {
        size_t i4 = (size_t)b * 256 + t;
        int m  = (int)(i4 >> 7);
        int c4 = ((int)i4 & 127) * 4;
        float4 v;
        if (c4 < IN1) v = *(const float4*)(x1 + (size_t)m * IN1 + c4);
        else          v = *(const float4*)(x2 + (size_t)m * IN2 + (c4 - IN1));
        size_t o = (size_t)m * KDIM + c4;
        *(__half2*)&g_Ah[o]     = __floats2half2_rn(v.x, v.y);
        *(__half2*)&g_Ah[o + 2] = __floats2half2_rn(v.z, v.w);
    } else if (b < NBA + NBW1) {
        int idx = (b - NBA) * 256 + t;      // < 589824
        int k = idx / N1, c = idx % N1;
        int g = c / G1U, j = c % G1U;
        int n = (j >> 4) * 48 + g * 16 + (j & 15);
        g_Bh[(size_t)n * KDIM + k] = __float2half_rn(W1[idx]);
    } else if (b < NBA + NBW1 + NBW2) {
        int idx = (b - NBA - NBW1) * 256 + t;
        if (idx < G1U * 48) {
            int k = idx / 48, c = idx % 48;
            g_B2[(size_t)c * G1U + k] = __float2half_rn(W2[idx]);
        }
    } else {
        // pack head weights: 4096 entries
#pragma unroll
        for (int i = 0; i < 16; ++i) {
            int idx = t + i * 256;
            g_Wh[idx] = __floats2half2_rn(hw1[idx], hw2[idx]);
        }
    }
}

// =====================================================================
// GEMM1: h1 = GRU1(A, h=0).  fp16 single-pass HMMA.  (champion config)
// CTA tile 128 x 96; 8 warps of 32x48.  K = 512 -> 8 tiles of 64.
// 3-stage cp.async, one barrier per k-tile, 2 CTAs/SM, fast gates.
// =====================================================================
#define G1_STAGE  28672            // 16KB A + 12KB B
#define G1_OFFB   16384
#define G1_NSTG   3
#define G1_BIAS   (G1_NSTG * G1_STAGE) // 86016
#define G1_SMEM   (G1_BIAS + 512)

__device__ __forceinline__ void load_stage_g1(u32 sb, int s, int kt, int m0, int nb, int tid)
{
    const int k0 = kt * 64;
    const u32 base = sb + s * G1_STAGE;
    const char* Ap = (const char*)g_Ah;
    const char* Bp = (const char*)g_Bh;
    // A tile: 128 rows x 128B
#pragma unroll
    for (int i = 0; i < 4; ++i) {
        int c = tid + i * 256;              // 0..1023
        int row = c >> 3, cb = c & 7;
        u32 dst = base + swz(row * 128 + cb * 16);
        const char* src = Ap + (size_t)(m0 + row) * (KDIM * 2) + k0 * 2 + cb * 16;
        CP_ASYNC16(dst, src);
    }
    // B tile: 96 rows x 128B
#pragma unroll
    for (int i = 0; i < 3; ++i) {
        int c = tid + i * 256;              // 0..767
        int row = c >> 3, cb = c & 7;
        u32 dst = base + G1_OFFB + swz(row * 128 + cb * 16);
        const char* src = Bp + (size_t)(nb * 96 + row) * (KDIM * 2) + k0 * 2 + cb * 16;
        CP_ASYNC16(dst, src);
    }
}

__global__ __launch_bounds__(256, 2)
void gemm1_mma_kernel(const float* __restrict__ bias)
{
    extern __shared__ char smem[];
    const u32 sb = smem_u32(smem);
    const int tid  = threadIdx.x;
    const int warp = tid >> 5, lane = tid & 31;
    const int wm = warp & 3;          // m block: 32*wm
    const int wn = warp >> 2;         // n block: 48*wn
    const int nb = blockIdx.x;        // 0..11  (32-unit block)
    const int m0 = blockIdx.y * 128;

    float* czs  = (float*)(smem + G1_BIAS);
    float* crs  = czs + 32;
    float* ch0s = czs + 64;
    float* ch1s = czs + 96;
    if (tid < 32) {
        int j = nb * 32 + tid;
        czs[tid]  = bias[j]         + bias[N1 + j];
        crs[tid]  = bias[G1U + j]   + bias[N1 + G1U + j];
        ch0s[tid] = bias[2 * G1U + j];
        ch1s[tid] = bias[N1 + 2 * G1U + j];
    }

    float acc[2][6][4];
#pragma unroll
    for (int mi = 0; mi < 2; ++mi)
#pragma unroll
        for (int ni = 0; ni < 6; ++ni)
#pragma unroll
            for (int e = 0; e < 4; ++e) acc[mi][ni][e] = 0.f;

    const int a_row = 32 * wm + (lane & 15);
    const int a_kb  = (lane & 16) ? 16 : 0;
    const int b_row = 48 * wn + (lane & 7) + ((lane & 16) ? 8 : 0);
    const int b_kb  = (lane & 8) ? 16 : 0;

    load_stage_g1(sb, 0, 0, m0, nb, tid); CP_COMMIT();
    load_stage_g1(sb, 1, 1, m0, nb, tid); CP_COMMIT();

    for (int kt = 0; kt < 8; ++kt) {
        const int s = kt % G1_NSTG;
        CP_WAIT1();
        __syncthreads();
        if (kt + 2 < 8) load_stage_g1(sb, (kt + 2) % G1_NSTG, kt + 2, m0, nb, tid);
        CP_COMMIT();

        const u32 abase = sb + s * G1_STAGE;
        const u32 bbase = abase + G1_OFFB;
#pragma unroll
        for (int ks = 0; ks < 4; ++ks) {
            u32 af[2][4], bf[3][4];
#pragma unroll
            for (int mi = 0; mi < 2; ++mi) {
                u32 ad = abase + swz((u32)(a_row + mi * 16) * 128 + ks * 32 + a_kb);
                LDSM_X4(af[mi][0], af[mi][1], af[mi][2], af[mi][3], ad);
            }
#pragma unroll
            for (int bi = 0; bi < 3; ++bi) {
                u32 bd = bbase + swz((u32)(b_row + bi * 16) * 128 + ks * 32 + b_kb);
                LDSM_X4(bf[bi][0], bf[bi][1], bf[bi][2], bf[bi][3], bd);
            }
#pragma unroll
            for (int mi = 0; mi < 2; ++mi)
#pragma unroll
                for (int bi = 0; bi < 3; ++bi) {
                    MMA16816(acc[mi][2 * bi],     af[mi], (&bf[bi][0]));
                    MMA16816(acc[mi][2 * bi + 1], af[mi], (&bf[bi][2]));
                }
        }
    }

    // ---- fused GRU epilogue (fast gates) ----
    const int qr = lane >> 2, qc = lane & 3;
#pragma unroll
    for (int mi = 0; mi < 2; ++mi) {
#pragma unroll
        for (int nip = 0; nip < 2; ++nip) {
            const int ul = wn * 16 + 8 * nip + 2 * qc;   // 0..31
            const int j0 = nb * 32 + ul;
            const float cz0 = czs[ul],  cz1 = czs[ul + 1];
            const float cr0 = crs[ul],  cr1 = crs[ul + 1];
            const float c00 = ch0s[ul], c01 = ch0s[ul + 1];
            const float c10 = ch1s[ul], c11 = ch1s[ul + 1];
            const float* az = acc[mi][nip];
            const float* ar = acc[mi][nip + 2];
            const float* ah = acc[mi][nip + 4];
#pragma unroll
            for (int half = 0; half < 2; ++half) {
                const int row = m0 + 32 * wm + 16 * mi + qr + half * 8;
                float z0 = sigmoid_fast(az[2 * half]     + cz0);
                float z1 = sigmoid_fast(az[2 * half + 1] + cz1);
                float r0 = sigmoid_fast(ar[2 * half]     + cr0);
                float r1 = sigmoid_fast(ar[2 * half + 1] + cr1);
                float h0 = tanh_fast(ah[2 * half]     + c00 + r0 * c10);
                float h1 = tanh_fast(ah[2 * half + 1] + c01 + r1 * c11);
                *(__half2*)&g_h1h[(size_t)row * G1U + j0] =
                    __floats2half2_rn((1.f - z0) * h0, (1.f - z1) * h1);
            }
        }
    }
}

// =====================================================================
// GEMM2: h2 = GRU2(h1, h=0).  fp16 single-pass HMMA.
// CTA tile 128 x 48; 8 warps of 16x48. K = 384 -> 6 tiles; 3-stage.
// =====================================================================
#define G2_STAGE  22528
#define G2_OFFB   16384
#define G2_BIAS   (3 * G2_STAGE) // 67584
#define G2_SMEM   (G2_BIAS + 512)

__device__ __forceinline__ void load_stage_g2(u32 sb, int s, int kt, int m0, int tid)
{
    const int k0 = kt * 64;
    const u32 base = sb + s * G2_STAGE;
    const char* Ap = (const char*)g_h1h;
    const char* Bp = (const char*)g_B2;
#pragma unroll
    for (int i = 0; i < 4; ++i) {
        int c = tid + i * 256;              // 0..1023
        int row = c >> 3, cb = c & 7;
        u32 dst = base + swz(row * 128 + cb * 16);
        const char* src = Ap + (size_t)(m0 + row) * (G1U * 2) + k0 * 2 + cb * 16;
        CP_ASYNC16(dst, src);
    }
#pragma unroll
    for (int i = 0; i < 2; ++i) {
        int c = tid + i * 256;
        if (c < 384) {
            int row = c >> 3, cb = c & 7;
            u32 dst = base + G2_OFFB + swz(row * 128 + cb * 16);
            const char* src = Bp + (size_t)row * (G1U * 2) + k0 * 2 + cb * 16;
            CP_ASYNC16(dst, src);
        }
    }
}

__global__ __launch_bounds__(256, 2)
void gemm2_mma_kernel(const float* __restrict__ bias)
{
    extern __shared__ char smem[];
    const u32 sb = smem_u32(smem);
    const int tid  = threadIdx.x;
    const int warp = tid >> 5, lane = tid & 31;
    const int m0 = blockIdx.x * 128;

    float* czs  = (float*)(smem + G2_BIAS);
    float* crs  = czs + 16;
    float* ch0s = czs + 32;
    float* ch1s = czs + 48;
    if (tid < 16) {
        czs[tid]  = bias[tid]      + bias[48 + tid];
        crs[tid]  = bias[16 + tid] + bias[64 + tid];
        ch0s[tid] = bias[32 + tid];
        ch1s[tid] = bias[80 + tid];
    }

    float acc[6][4];
#pragma unroll
    for (int ni = 0; ni < 6; ++ni)
#pragma unroll
        for (int e = 0; e < 4; ++e) acc[ni][e] = 0.f;

    const int a_row = 16 * warp + (lane & 15);
    const int a_kb  = (lane & 16) ? 16 : 0;
    const int b_row = (lane & 7) + ((lane & 16) ? 8 : 0);
    const int b_kb  = (lane & 8) ? 16 : 0;

    load_stage_g2(sb, 0, 0, m0, tid); CP_COMMIT();
    load_stage_g2(sb, 1, 1, m0, tid); CP_COMMIT();

    for (int kt = 0; kt < 6; ++kt) {
        const int s = kt % 3;
        CP_WAIT1();
        __syncthreads();
        if (kt + 2 < 6) load_stage_g2(sb, (kt + 2) % 3, kt + 2, m0, tid);
        CP_COMMIT();

        const u32 abase = sb + s * G2_STAGE;
        const u32 bbase = abase + G2_OFFB;
#pragma unroll
        for (int ks = 0; ks < 4; ++ks) {
            u32 af[4], bf[3][4];
            u32 ad = abase + swz((u32)a_row * 128 + ks * 32 + a_kb);
            LDSM_X4(af[0], af[1], af[2], af[3], ad);
#pragma unroll
            for (int bi = 0; bi < 3; ++bi) {
                u32 bd = bbase + swz((u32)(b_row + bi * 16) * 128 + ks * 32 + b_kb);
                LDSM_X4(bf[bi][0], bf[bi][1], bf[bi][2], bf[bi][3], bd);
            }
#pragma unroll
            for (int bi = 0; bi < 3; ++bi) {
                MMA16816(acc[2 * bi],     af, (&bf[bi][0]));
                MMA16816(acc[2 * bi + 1], af, (&bf[bi][2]));
            }
        }
    }

    const int qr = lane >> 2, qc = lane & 3;
#pragma unroll
    for (int nip = 0; nip < 2; ++nip) {
        const int u0 = 8 * nip + 2 * qc;
        const float cz0 = czs[u0],  cz1 = czs[u0 + 1];
        const float cr0 = crs[u0],  cr1 = crs[u0 + 1];
        const float c00 = ch0s[u0], c01 = ch0s[u0 + 1];
        const float c10 = ch1s[u0], c11 = ch1s[u0 + 1];
        const float* az = acc[nip];
        const float* ar = acc[nip + 2];
        const float* ah = acc[nip + 4];
#pragma unroll
        for (int half = 0; half < 2; ++half) {
            const int row = m0 + 16 * warp + qr + half * 8;
            float z0 = sigmoid_fast(az[2 * half]     + cz0);
            float z1 = sigmoid_fast(az[2 * half + 1] + cz1);
            float r0 = sigmoid_fast(ar[2 * half]     + cr0);
            float r1 = sigmoid_fast(ar[2 * half + 1] + cr1);
            float h0 = tanh_fast(ah[2 * half]     + c00 + r0 * c10);
            float h1 = tanh_fast(ah[2 * half + 1] + c01 + r1 * c11);
            *(float2*)&g_h2[(size_t)row * G2U + u0] =
                make_float2((1.f - z0) * h0, (1.f - z1) * h1);
        }
    }
}

// =====================================================================
// Kernel 3: head + softmax.  Packed half2 (w1,w2) weights: one LDS.32
// per (k,q) serves 4 FFMAs -> smem crossbar traffic halved.
// =====================================================================
__global__ __launch_bounds__(256)
void head_kernel(const float* __restrict__ b1, const float* __restrict__ b2,
                 const float* __restrict__ gv1, const float* __restrict__ gv2,
                 float* __restrict__ out)
{
    __shared__ __half2 Ws[16 * NLEV];     // packed (w1,w2)
    __shared__ float b1s[NLEV], b2s[NLEV], g1s[NLEV], g2s[NLEV];

    const int t = threadIdx.x;
    for (int i = t; i < 16 * NLEV; i += 256) Ws[i] = g_Wh[i];
    b1s[t] = b1[t]; b2s[t] = b2[t]; g1s[t] = gv1[t]; g2s[t] = gv2[t];
    __syncthreads();

    const int warp = t >> 5, lane = t & 31;
    const int gwarp = blockIdx.x * 8 + warp;

    for (int p = 0; p < 4; ++p) {
        const int r0 = gwarp * 8 + p * 2;
        float ha[16], hb[16];
        {
            const float4* pa = (const float4*)&g_h2[(size_t)r0 * G2U];
            const float4* pb = (const float4*)&g_h2[(size_t)(r0 + 1) * G2U];
#pragma unroll
            for (int i = 0; i < 4; ++i) {
                float4 va = __ldg(pa + i);
                float4 vb = __ldg(pb + i);
                ha[4*i] = va.x; ha[4*i+1] = va.y; ha[4*i+2] = va.z; ha[4*i+3] = va.w;
                hb[4*i] = vb.x; hb[4*i+1] = vb.y; hb[4*i+2] = vb.z; hb[4*i+3] = vb.w;
            }
        }
        float a1a[8], a2a[8], a1b[8], a2b[8];
#pragma unroll
        for (int q = 0; q < 8; ++q) { a1a[q]=0.f; a2a[q]=0.f; a1b[q]=0.f; a2b[q]=0.f; }
#pragma unroll
        for (int k = 0; k < 16; ++k) {
            const float hka = ha[k], hkb = hb[k];
#pragma unroll
            for (int q = 0; q < 8; ++q) {
                const int l = lane + 32 * q;
                float2 wv = __half22float2(Ws[k * NLEV + l]);
                a1a[q] = fmaf(hka, wv.x, a1a[q]);
                a2a[q] = fmaf(hka, wv.y, a2a[q]);
                a1b[q] = fmaf(hkb, wv.x, a1b[q]);
                a2b[q] = fmaf(hkb, wv.y, a2b[q]);
            }
        }
#pragma unroll
        for (int ri = 0; ri < 2; ++ri) {
            float v[8];
#pragma unroll
            for (int q = 0; q < 8; ++q) {
                const int l = lane + 32 * q;
                const float t1 = tanh_fast((ri ? a1b[q] : a1a[q]) + b1s[l]);
                const float t2 = tanh_fast((ri ? a2b[q] : a2a[q]) + b2s[l]);
                v[q] = g1s[l] * t1 + g2s[l] * t2;
            }
            float mx = v[0];
#pragma unroll
            for (int q = 1; q < 8; ++q) mx = fmaxf(mx, v[q]);
#pragma unroll
            for (int off = 16; off >= 1; off >>= 1)
                mx = fmaxf(mx, __shfl_xor_sync(0xffffffffu, mx, off));
            float e[8], s = 0.f;
#pragma unroll
            for (int q = 0; q < 8; ++q) { e[q] = __expf(v[q] - mx); s += e[q]; }
#pragma unroll
            for (int off = 16; off >= 1; off >>= 1)
                s += __shfl_xor_sync(0xffffffffu, s, off);
            const float inv = 1.0f / s;
            float* orow = out + (size_t)(r0 + ri) * NLEV;
#pragma unroll
            for (int q = 0; q < 8; ++q)
                orow[lane + 32 * q] = e[q] * inv;
        }
    }
}

// =====================================================================
extern "C" void kernel_launch(void* const* d_in, const int* in_sizes, int n_in,
                              void* d_out, int out_size)
{
    const float* x1   = (const float*)d_in[0];
    const float* x2   = (const float*)d_in[1];
    const float* g1k  = (const float*)d_in[2];
    const float* g1b  = (const float*)d_in[4];
    const float* g2k  = (const float*)d_in[5];
    const float* g2b  = (const float*)d_in[7];
    const float* fw1  = (const float*)d_in[8];
    const float* fb1  = (const float*)d_in[9];
    const float* fw2  = (const float*)d_in[10];
    const float* fb2  = (const float*)d_in[11];
    const float* fg1  = (const float*)d_in[12];
    const float* fg2  = (const float*)d_in[13];
    float* out = (float*)d_out;

    cudaFuncSetAttribute(gemm1_mma_kernel,
                         cudaFuncAttributeMaxDynamicSharedMemorySize, G1_SMEM);
    cudaFuncSetAttribute(gemm2_mma_kernel,
                         cudaFuncAttributeMaxDynamicSharedMemorySize, G2_SMEM);

    prep_kernel<<<NPREP, 256>>>(x1, x2, g1k, g2k, fw1, fw2);
    gemm1_mma_kernel<<<dim3(12, NB / 128), 256, G1_SMEM>>>(g1b);
    gemm2_mma_kernel<<<NB / 128, 256, G2_SMEM>>>(g2b);
    head_kernel<<<NB / 64, 256>>>(fb1, fb2, fg1, fg2, out);
}

// round 12
// speedup vs baseline: 1.4683x; 1.0702x over previous
#include <cuda_runtime.h>
#include <cuda_fp16.h>
#include <cstdint>

// ---------------- problem constants ----------------
#define NB     65536
#define IN1    384
#define IN2    128
#define KDIM   512
#define G1U    384
#define N1     1152
#define G2U    16
#define NLEV   256

typedef unsigned long long u64;
typedef unsigned int u32;

// ---------------- device scratch ----------------
__device__ __half g_Ah[(size_t)NB * KDIM];     // 64 MB  fp16 concat(x1,x2)
__device__ __half g_Bh[(size_t)N1 * KDIM];     // reordered+transposed W1
__device__ __half g_h1h[(size_t)NB * G1U];     // 48 MB  fp16 h1
__device__ __half g_B2[(size_t)48 * G1U];      // transposed W2
__device__ __half g_h2h[(size_t)NB * G2U];     // 2 MB   fp16 h2
__device__ u32    g_Wf1[2048];                 // head W1 in MMA B-fragment order
__device__ u32    g_Wf2[2048];                 // head W2 in MMA B-fragment order

// ---------------- helpers ----------------
__device__ __forceinline__ u32 smem_u32(const void* p) {
    u32 a;
    asm("{ .reg .u64 t; cvta.to.shared.u64 t, %1; cvt.u32.u64 %0, t; }" : "=r"(a) : "l"(p));
    return a;
}
__device__ __forceinline__ u32 swz(u32 x) { return x ^ ((x >> 3) & 0x70); }

#define CP_ASYNC16(dst, src) \
    asm volatile("cp.async.cg.shared.global [%0], [%1], 16;" :: "r"(dst), "l"(src) : "memory")
#define CP_COMMIT() asm volatile("cp.async.commit_group;" ::: "memory")
#define CP_WAIT1()  asm volatile("cp.async.wait_group 1;" ::: "memory")

#define LDSM_X4(r0, r1, r2, r3, addr) \
    asm volatile("ldmatrix.sync.aligned.m8n8.x4.shared.b16 {%0,%1,%2,%3}, [%4];" \
        : "=r"(r0), "=r"(r1), "=r"(r2), "=r"(r3) : "r"(addr))

#define MMA16816(d, a, b) \
    asm volatile("mma.sync.aligned.m16n8k16.row.col.f32.f16.f16.f32 " \
        "{%0,%1,%2,%3},{%4,%5,%6,%7},{%8,%9},{%0,%1,%2,%3};" \
        : "+f"((d)[0]), "+f"((d)[1]), "+f"((d)[2]), "+f"((d)[3]) \
        : "r"((a)[0]), "r"((a)[1]), "r"((a)[2]), "r"((a)[3]), "r"((b)[0]), "r"((b)[1]))

// ---- fast gate math: 1 MUFU per tanh ----
__device__ __forceinline__ float tanh_fast(float x) {
    float y;
    asm("tanh.approx.f32 %0, %1;" : "=f"(y) : "f"(x));
    return y;
}
__device__ __forceinline__ float sigmoid_fast(float x) {
    return fmaf(0.5f, tanh_fast(0.5f * x), 0.5f);
}

// =====================================================================
// Combined prep kernel (single launch):
//  blocks [0, NBA)            : A = concat(x1,x2) -> fp16
//  blocks [NBA, NBA+NBW1)     : W1 transpose+reorder -> fp16
//  blocks [.., +NBW2)         : W2 transpose -> fp16
//  last block                 : head weights -> MMA B-fragment order
// =====================================================================
#define NBA   (NB * (KDIM / 4) / 256)     // 16384
#define NBW1  ((KDIM * N1) / 256)         // 2304
#define NBW2  ((G1U * 48 + 255) / 256)    // 72
#define NPREP (NBA + NBW1 + NBW2 + 1)

__global__ __launch_bounds__(256)
void prep_kernel(const float* __restrict__ x1, const float* __restrict__ x2,
                 const float* __restrict__ W1, const float* __restrict__ W2,
                 const float* __restrict__ hw1, const float* __restrict__ hw2)
{
    const int b = blockIdx.x;
    const int t = threadIdx.x;
    if (b < NBA) {
        size_t i4 = (size_t)b * 256 + t;
        int m  = (int)(i4 >> 7);
        int c4 = ((int)i4 & 127) * 4;
        float4 v;
        if (c4 < IN1) v = *(const float4*)(x1 + (size_t)m * IN1 + c4);
        else          v = *(const float4*)(x2 + (size_t)m * IN2 + (c4 - IN1));
        size_t o = (size_t)m * KDIM + c4;
        *(__half2*)&g_Ah[o]     = __floats2half2_rn(v.x, v.y);
        *(__half2*)&g_Ah[o + 2] = __floats2half2_rn(v.z, v.w);
    } else if (b < NBA + NBW1) {
        int idx = (b - NBA) * 256 + t;      // < 589824
        int k = idx / N1, c = idx % N1;
        int g = c / G1U, j = c % G1U;
        int n = (j >> 4) * 48 + g * 16 + (j & 15);
        g_Bh[(size_t)n * KDIM + k] = __float2half_rn(W1[idx]);
    } else if (b < NBA + NBW1 + NBW2) {
        int idx = (b - NBA - NBW1) * 256 + t;
        if (idx < G1U * 48) {
            int k = idx / 48, c = idx % 48;
            g_B2[(size_t)c * G1U + k] = __float2half_rn(W2[idx]);
        }
    } else {
        // Head weights -> m16n8k16 B-fragment order:
        // entry i = tile*32 + lane; k0=(lane&3)*2, n=tile*8+(lane>>2)
        // frag reg0 = (W[k0][n], W[k0+1][n]), reg1 = (W[k0+8][n], W[k0+9][n])
#pragma unroll
        for (int i = t; i < 1024; i += 256) {
            int tt = i >> 5, lane = i & 31;
            int k0 = (lane & 3) * 2;
            int n  = tt * 8 + (lane >> 2);
            __half2 p10 = __floats2half2_rn(hw1[k0 * NLEV + n],       hw1[(k0 + 1) * NLEV + n]);
            __half2 p11 = __floats2half2_rn(hw1[(k0 + 8) * NLEV + n], hw1[(k0 + 9) * NLEV + n]);
            __half2 p20 = __floats2half2_rn(hw2[k0 * NLEV + n],       hw2[(k0 + 1) * NLEV + n]);
            __half2 p21 = __floats2half2_rn(hw2[(k0 + 8) * NLEV + n], hw2[(k0 + 9) * NLEV + n]);
            g_Wf1[2 * i]     = *(u32*)&p10;
            g_Wf1[2 * i + 1] = *(u32*)&p11;
            g_Wf2[2 * i]     = *(u32*)&p20;
            g_Wf2[2 * i + 1] = *(u32*)&p21;
        }
    }
}

// =====================================================================
// GEMM1: h1 = GRU1(A, h=0).  fp16 single-pass HMMA.  (champion config)
// CTA tile 128 x 96; 8 warps of 32x48.  K = 512 -> 8 tiles of 64.
// 3-stage cp.async, one barrier per k-tile, 2 CTAs/SM, fast gates.
// =====================================================================
#define G1_STAGE  28672            // 16KB A + 12KB B
#define G1_OFFB   16384
#define G1_NSTG   3
#define G1_BIAS   (G1_NSTG * G1_STAGE) // 86016
#define G1_SMEM   (G1_BIAS + 512)

__device__ __forceinline__ void load_stage_g1(u32 sb, int s, int kt, int m0, int nb, int tid)
{
    const int k0 = kt * 64;
    const u32 base = sb + s * G1_STAGE;
    const char* Ap = (const char*)g_Ah;
    const char* Bp = (const char*)g_Bh;
#pragma unroll
    for (int i = 0; i < 4; ++i) {
        int c = tid + i * 256;              // 0..1023
        int row = c >> 3, cb = c & 7;
        u32 dst = base + swz(row * 128 + cb * 16);
        const char* src = Ap + (size_t)(m0 + row) * (KDIM * 2) + k0 * 2 + cb * 16;
        CP_ASYNC16(dst, src);
    }
#pragma unroll
    for (int i = 0; i < 3; ++i) {
        int c = tid + i * 256;              // 0..767
        int row = c >> 3, cb = c & 7;
        u32 dst = base + G1_OFFB + swz(row * 128 + cb * 16);
        const char* src = Bp + (size_t)(nb * 96 + row) * (KDIM * 2) + k0 * 2 + cb * 16;
        CP_ASYNC16(dst, src);
    }
}

__global__ __launch_bounds__(256, 2)
void gemm1_mma_kernel(const float* __restrict__ bias)
{
    extern __shared__ char smem[];
    const u32 sb = smem_u32(smem);
    const int tid  = threadIdx.x;
    const int warp = tid >> 5, lane = tid & 31;
    const int wm = warp & 3;
    const int wn = warp >> 2;
    const int nb = blockIdx.x;
    const int m0 = blockIdx.y * 128;

    float* czs  = (float*)(smem + G1_BIAS);
    float* crs  = czs + 32;
    float* ch0s = czs + 64;
    float* ch1s = czs + 96;
    if (tid < 32) {
        int j = nb * 32 + tid;
        czs[tid]  = bias[j]         + bias[N1 + j];
        crs[tid]  = bias[G1U + j]   + bias[N1 + G1U + j];
        ch0s[tid] = bias[2 * G1U + j];
        ch1s[tid] = bias[N1 + 2 * G1U + j];
    }

    float acc[2][6][4];
#pragma unroll
    for (int mi = 0; mi < 2; ++mi)
#pragma unroll
        for (int ni = 0; ni < 6; ++ni)
#pragma unroll
            for (int e = 0; e < 4; ++e) acc[mi][ni][e] = 0.f;

    const int a_row = 32 * wm + (lane & 15);
    const int a_kb  = (lane & 16) ? 16 : 0;
    const int b_row = 48 * wn + (lane & 7) + ((lane & 16) ? 8 : 0);
    const int b_kb  = (lane & 8) ? 16 : 0;

    load_stage_g1(sb, 0, 0, m0, nb, tid); CP_COMMIT();
    load_stage_g1(sb, 1, 1, m0, nb, tid); CP_COMMIT();

    for (int kt = 0; kt < 8; ++kt) {
        const int s = kt % G1_NSTG;
        CP_WAIT1();
        __syncthreads();
        if (kt + 2 < 8) load_stage_g1(sb, (kt + 2) % G1_NSTG, kt + 2, m0, nb, tid);
        CP_COMMIT();

        const u32 abase = sb + s * G1_STAGE;
        const u32 bbase = abase + G1_OFFB;
#pragma unroll
        for (int ks = 0; ks < 4; ++ks) {
            u32 af[2][4], bf[3][4];
#pragma unroll
            for (int mi = 0; mi < 2; ++mi) {
                u32 ad = abase + swz((u32)(a_row + mi * 16) * 128 + ks * 32 + a_kb);
                LDSM_X4(af[mi][0], af[mi][1], af[mi][2], af[mi][3], ad);
            }
#pragma unroll
            for (int bi = 0; bi < 3; ++bi) {
                u32 bd = bbase + swz((u32)(b_row + bi * 16) * 128 + ks * 32 + b_kb);
                LDSM_X4(bf[bi][0], bf[bi][1], bf[bi][2], bf[bi][3], bd);
            }
#pragma unroll
            for (int mi = 0; mi < 2; ++mi)
#pragma unroll
                for (int bi = 0; bi < 3; ++bi) {
                    MMA16816(acc[mi][2 * bi],     af[mi], (&bf[bi][0]));
                    MMA16816(acc[mi][2 * bi + 1], af[mi], (&bf[bi][2]));
                }
        }
    }

    // ---- fused GRU epilogue (fast gates) ----
    const int qr = lane >> 2, qc = lane & 3;
#pragma unroll
    for (int mi = 0; mi < 2; ++mi) {
#pragma unroll
        for (int nip = 0; nip < 2; ++nip) {
            const int ul = wn * 16 + 8 * nip + 2 * qc;
            const int j0 = nb * 32 + ul;
            const float cz0 = czs[ul],  cz1 = czs[ul + 1];
            const float cr0 = crs[ul],  cr1 = crs[ul + 1];
            const float c00 = ch0s[ul], c01 = ch0s[ul + 1];
            const float c10 = ch1s[ul], c11 = ch1s[ul + 1];
            const float* az = acc[mi][nip];
            const float* ar = acc[mi][nip + 2];
            const float* ah = acc[mi][nip + 4];
#pragma unroll
            for (int half = 0; half < 2; ++half) {
                const int row = m0 + 32 * wm + 16 * mi + qr + half * 8;
                float z0 = sigmoid_fast(az[2 * half]     + cz0);
                float z1 = sigmoid_fast(az[2 * half + 1] + cz1);
                float r0 = sigmoid_fast(ar[2 * half]     + cr0);
                float r1 = sigmoid_fast(ar[2 * half + 1] + cr1);
                float h0 = tanh_fast(ah[2 * half]     + c00 + r0 * c10);
                float h1 = tanh_fast(ah[2 * half + 1] + c01 + r1 * c11);
                *(__half2*)&g_h1h[(size_t)row * G1U + j0] =
                    __floats2half2_rn((1.f - z0) * h0, (1.f - z1) * h1);
            }
        }
    }
}

// =====================================================================
// GEMM2: h2 = GRU2(h1, h=0) -> fp16 g_h2h.  (otherwise unchanged)
// =====================================================================
#define G2_STAGE  22528
#define G2_OFFB   16384
#define G2_BIAS   (3 * G2_STAGE) // 67584
#define G2_SMEM   (G2_BIAS + 512)

__device__ __forceinline__ void load_stage_g2(u32 sb, int s, int kt, int m0, int tid)
{
    const int k0 = kt * 64;
    const u32 base = sb + s * G2_STAGE;
    const char* Ap = (const char*)g_h1h;
    const char* Bp = (const char*)g_B2;
#pragma unroll
    for (int i = 0; i < 4; ++i) {
        int c = tid + i * 256;              // 0..1023
        int row = c >> 3, cb = c & 7;
        u32 dst = base + swz(row * 128 + cb * 16);
        const char* src = Ap + (size_t)(m0 + row) * (G1U * 2) + k0 * 2 + cb * 16;
        CP_ASYNC16(dst, src);
    }
#pragma unroll
    for (int i = 0; i < 2; ++i) {
        int c = tid + i * 256;
        if (c < 384) {
            int row = c >> 3, cb = c & 7;
            u32 dst = base + G2_OFFB + swz(row * 128 + cb * 16);
            const char* src = Bp + (size_t)row * (G1U * 2) + k0 * 2 + cb * 16;
            CP_ASYNC16(dst, src);
        }
    }
}

__global__ __launch_bounds__(256, 2)
void gemm2_mma_kernel(const float* __restrict__ bias)
{
    extern __shared__ char smem[];
    const u32 sb = smem_u32(smem);
    const int tid  = threadIdx.x;
    const int warp = tid >> 5, lane = tid & 31;
    const int m0 = blockIdx.x * 128;

    float* czs  = (float*)(smem + G2_BIAS);
    float* crs  = czs + 16;
    float* ch0s = czs + 32;
    float* ch1s = czs + 48;
    if (tid < 16) {
        czs[tid]  = bias[tid]      + bias[48 + tid];
        crs[tid]  = bias[16 + tid] + bias[64 + tid];
        ch0s[tid] = bias[32 + tid];
        ch1s[tid] = bias[80 + tid];
    }

    float acc[6][4];
#pragma unroll
    for (int ni = 0; ni < 6; ++ni)
#pragma unroll
        for (int e = 0; e < 4; ++e) acc[ni][e] = 0.f;

    const int a_row = 16 * warp + (lane & 15);
    const int a_kb  = (lane & 16) ? 16 : 0;
    const int b_row = (lane & 7) + ((lane & 16) ? 8 : 0);
    const int b_kb  = (lane & 8) ? 16 : 0;

    load_stage_g2(sb, 0, 0, m0, tid); CP_COMMIT();
    load_stage_g2(sb, 1, 1, m0, tid); CP_COMMIT();

    for (int kt = 0; kt < 6; ++kt) {
        const int s = kt % 3;
        CP_WAIT1();
        __syncthreads();
        if (kt + 2 < 6) load_stage_g2(sb, (kt + 2) % 3, kt + 2, m0, tid);
        CP_COMMIT();

        const u32 abase = sb + s * G2_STAGE;
        const u32 bbase = abase + G2_OFFB;
#pragma unroll
        for (int ks = 0; ks < 4; ++ks) {
            u32 af[4], bf[3][4];
            u32 ad = abase + swz((u32)a_row * 128 + ks * 32 + a_kb);
            LDSM_X4(af[0], af[1], af[2], af[3], ad);
#pragma unroll
            for (int bi = 0; bi < 3; ++bi) {
                u32 bd = bbase + swz((u32)(b_row + bi * 16) * 128 + ks * 32 + b_kb);
                LDSM_X4(bf[bi][0], bf[bi][1], bf[bi][2], bf[bi][3], bd);
            }
#pragma unroll
            for (int bi = 0; bi < 3; ++bi) {
                MMA16816(acc[2 * bi],     af, (&bf[bi][0]));
                MMA16816(acc[2 * bi + 1], af, (&bf[bi][2]));
            }
        }
    }

    const int qr = lane >> 2, qc = lane & 3;
#pragma unroll
    for (int nip = 0; nip < 2; ++nip) {
        const int u0 = 8 * nip + 2 * qc;
        const float cz0 = czs[u0],  cz1 = czs[u0 + 1];
        const float cr0 = crs[u0],  cr1 = crs[u0 + 1];
        const float c00 = ch0s[u0], c01 = ch0s[u0 + 1];
        const float c10 = ch1s[u0], c11 = ch1s[u0 + 1];
        const float* az = acc[nip];
        const float* ar = acc[nip + 2];
        const float* ah = acc[nip + 4];
#pragma unroll
        for (int half = 0; half < 2; ++half) {
            const int row = m0 + 16 * warp + qr + half * 8;
            float z0 = sigmoid_fast(az[2 * half]     + cz0);
            float z1 = sigmoid_fast(az[2 * half + 1] + cz1);
            float r0 = sigmoid_fast(ar[2 * half]     + cr0);
            float r1 = sigmoid_fast(ar[2 * half + 1] + cr1);
            float h0 = tanh_fast(ah[2 * half]     + c00 + r0 * c10);
            float h1 = tanh_fast(ah[2 * half + 1] + c01 + r1 * c11);
            *(__half2*)&g_h2h[(size_t)row * G2U + u0] =
                __floats2half2_rn((1.f - z0) * h0, (1.f - z1) * h1);
        }
    }
}

// =====================================================================
// HEAD via HMMA: per warp, 16 rows. A-frag = h2 rows (fp16 from gmem),
// B-frags = pre-packed weight fragments (smem). 32 n-tiles of 8 levels.
// Logits kept in registers; softmax = in-lane reduce + quad shfl.
// =====================================================================
__global__ __launch_bounds__(256, 1)
void head_mma_kernel(const float* __restrict__ b1, const float* __restrict__ b2,
                     const float* __restrict__ gv1, const float* __restrict__ gv2,
                     float* __restrict__ out)
{
    __shared__ u32 Wf1s[2048], Wf2s[2048];
    __shared__ float b1s[NLEV], b2s[NLEV], g1s[NLEV], g2s[NLEV];

    const int t = threadIdx.x;
    for (int i = t; i < 2048; i += 256) { Wf1s[i] = g_Wf1[i]; Wf2s[i] = g_Wf2[i]; }
    b1s[t] = b1[t]; b2s[t] = b2[t]; g1s[t] = gv1[t]; g2s[t] = gv2[t];
    __syncthreads();

    const int warp = t >> 5, lane = t & 31;
    const int qr = lane >> 2, qc = lane & 3;
    const int rbase = blockIdx.x * 128 + warp * 16;

    // A fragment: rows (qr, qr+8), k = 2qc..2qc+1 and +8
    const __half* h2p = g_h2h + (size_t)rbase * G2U;
    u32 a[4];
    a[0] = *(const u32*)&h2p[qr * G2U + 2 * qc];
    a[1] = *(const u32*)&h2p[(qr + 8) * G2U + 2 * qc];
    a[2] = *(const u32*)&h2p[qr * G2U + 2 * qc + 8];
    a[3] = *(const u32*)&h2p[(qr + 8) * G2U + 2 * qc + 8];

    float v[32][4];
    float mx0 = -1e30f, mx1 = -1e30f;
#pragma unroll
    for (int tt = 0; tt < 32; ++tt) {
        const int fi = (tt * 32 + lane) * 2;
        u32 bw1[2] = { Wf1s[fi], Wf1s[fi + 1] };
        u32 bw2[2] = { Wf2s[fi], Wf2s[fi + 1] };
        const int l = tt * 8 + 2 * qc;
        const float B1x = b1s[l], B1y = b1s[l + 1];
        const float B2x = b2s[l], B2y = b2s[l + 1];
        const float G1x = g1s[l], G1y = g1s[l + 1];
        const float G2x = g2s[l], G2y = g2s[l + 1];
        float d[4] = { B1x, B1y, B1x, B1y };
        float e[4] = { B2x, B2y, B2x, B2y };
        MMA16816(d, a, bw1);
        MMA16816(e, a, bw2);
        v[tt][0] = G1x * tanh_fast(d[0]) + G2x * tanh_fast(e[0]);
        v[tt][1] = G1y * tanh_fast(d[1]) + G2y * tanh_fast(e[1]);
        v[tt][2] = G1x * tanh_fast(d[2]) + G2x * tanh_fast(e[2]);
        v[tt][3] = G1y * tanh_fast(d[3]) + G2y * tanh_fast(e[3]);
        mx0 = fmaxf(mx0, fmaxf(v[tt][0], v[tt][1]));
        mx1 = fmaxf(mx1, fmaxf(v[tt][2], v[tt][3]));
    }
    // reduce max over the 4 lanes sharing each row (lane bits 0,1)
    mx0 = fmaxf(mx0, __shfl_xor_sync(0xffffffffu, mx0, 1));
    mx0 = fmaxf(mx0, __shfl_xor_sync(0xffffffffu, mx0, 2));
    mx1 = fmaxf(mx1, __shfl_xor_sync(0xffffffffu, mx1, 1));
    mx1 = fmaxf(mx1, __shfl_xor_sync(0xffffffffu, mx1, 2));

    float s0 = 0.f, s1 = 0.f;
#pragma unroll
    for (int tt = 0; tt < 32; ++tt) {
        v[tt][0] = __expf(v[tt][0] - mx0);
        v[tt][1] = __expf(v[tt][1] - mx0);
        v[tt][2] = __expf(v[tt][2] - mx1);
        v[tt][3] = __expf(v[tt][3] - mx1);
        s0 += v[tt][0] + v[tt][1];
        s1 += v[tt][2] + v[tt][3];
    }
    s0 += __shfl_xor_sync(0xffffffffu, s0, 1);
    s0 += __shfl_xor_sync(0xffffffffu, s0, 2);
    s1 += __shfl_xor_sync(0xffffffffu, s1, 1);
    s1 += __shfl_xor_sync(0xffffffffu, s1, 2);
    const float i0 = __fdividef(1.f, s0);
    const float i1 = __fdividef(1.f, s1);

    float* o0 = out + (size_t)(rbase + qr) * NLEV;
    float* o1 = out + (size_t)(rbase + qr + 8) * NLEV;
#pragma unroll
    for (int tt = 0; tt < 32; ++tt) {
        const int l = tt * 8 + 2 * qc;
        *(float2*)&o0[l] = make_float2(v[tt][0] * i0, v[tt][1] * i0);
        *(float2*)&o1[l] = make_float2(v[tt][2] * i1, v[tt][3] * i1);
    }
}

// =====================================================================
extern "C" void kernel_launch(void* const* d_in, const int* in_sizes, int n_in,
                              void* d_out, int out_size)
{
    const float* x1   = (const float*)d_in[0];
    const float* x2   = (const float*)d_in[1];
    const float* g1k  = (const float*)d_in[2];
    const float* g1b  = (const float*)d_in[4];
    const float* g2k  = (const float*)d_in[5];
    const float* g2b  = (const float*)d_in[7];
    const float* fw1  = (const float*)d_in[8];
    const float* fb1  = (const float*)d_in[9];
    const float* fw2  = (const float*)d_in[10];
    const float* fb2  = (const float*)d_in[11];
    const float* fg1  = (const float*)d_in[12];
    const float* fg2  = (const float*)d_in[13];
    float* out = (float*)d_out;

    cudaFuncSetAttribute(gemm1_mma_kernel,
                         cudaFuncAttributeMaxDynamicSharedMemorySize, G1_SMEM);
    cudaFuncSetAttribute(gemm2_mma_kernel,
                         cudaFuncAttributeMaxDynamicSharedMemorySize, G2_SMEM);

    prep_kernel<<<NPREP, 256>>>(x1, x2, g1k, g2k, fw1, fw2);
    gemm1_mma_kernel<<<dim3(12, NB / 128), 256, G1_SMEM>>>(g1b);
    gemm2_mma_kernel<<<NB / 128, 256, G2_SMEM>>>(g2b);
    head_mma_kernel<<<NB / 128, 256>>>(fb1, fb2, fg1, fg2, out);
}